// round 9
// baseline (speedup 1.0000x reference)
#include <cuda_runtime.h>
#include <cuda_bf16.h>
#include <math.h>

#define BATCH 1024
#define SEQ   1024
#define TAGS  32
#define ITERS 511          // main-loop iterations per direction

__device__ float g_logz[BATCH];
__device__ float g_gold[BATCH];

// ---------- packed f32x2 helpers (sm_103a FFMA2 path, PTX-only) ----------
__device__ __forceinline__ unsigned long long pk2(float x, float y) {
    unsigned long long r;
    asm("mov.b64 %0, {%1, %2};" : "=l"(r) : "f"(x), "f"(y));
    return r;
}
__device__ __forceinline__ void upk2(unsigned long long a, float& x, float& y) {
    asm("mov.b64 {%0, %1}, %2;" : "=f"(x), "=f"(y) : "l"(a));
}
__device__ __forceinline__ unsigned long long mul2(unsigned long long a, unsigned long long b) {
    unsigned long long d;
    asm("mul.rn.f32x2 %0, %1, %2;" : "=l"(d) : "l"(a), "l"(b));
    return d;
}
__device__ __forceinline__ unsigned long long fma2(unsigned long long a, unsigned long long b, unsigned long long c) {
    unsigned long long d;
    asm("fma.rn.f32x2 %0, %1, %2, %3;" : "=l"(d) : "l"(a), "l"(b), "l"(c));
    return d;
}
__device__ __forceinline__ unsigned long long add2(unsigned long long a, unsigned long long b) {
    unsigned long long d;
    asm("add.rn.f32x2 %0, %1, %2;" : "=l"(d) : "l"(a), "l"(b));
    return d;
}
__device__ __forceinline__ float ex2f(float x) {
    float y; asm("ex2.approx.f32 %0, %1;" : "=f"(y) : "f"(x)); return y;
}
__device__ __forceinline__ float lg2f(float x) {
    float y; asm("lg2.approx.f32 %0, %1;" : "=f"(y) : "f"(x)); return y;
}
__device__ __forceinline__ float rcpf(float x) {
    float y; asm("rcp.approx.f32 %0, %1;" : "=f"(y) : "f"(x)); return y;
}

#define LOG2E 1.4426950408889634f
#define LN2   0.6931471805599453f

// shared matvec: s_j = sum_i w_i * e-pairs. Also returns w0 (= wb[0]) from the
// already-loaded q0 register so renorm never issues an extra on-chain LDS.
__device__ __forceinline__ float matvec32(const float* wb,
                                          const unsigned long long* e,
                                          float& w0_out) {
    const ulonglong2* w4 = (const ulonglong2*)wb;
    ulonglong2 q0 = w4[0], q1 = w4[1], q2 = w4[2], q3 = w4[3];
    {
        float a, bdum; upk2(q0.x, a, bdum); w0_out = a;
    }
    unsigned long long a0 = mul2(q0.x, e[0]);
    unsigned long long a1 = mul2(q0.y, e[1]);
    unsigned long long a2 = mul2(q1.x, e[2]);
    unsigned long long a3 = mul2(q1.y, e[3]);
    a0 = fma2(q2.x, e[4], a0);
    a1 = fma2(q2.y, e[5], a1);
    a2 = fma2(q3.x, e[6], a2);
    a3 = fma2(q3.y, e[7], a3);
    ulonglong2 q4 = w4[4], q5 = w4[5], q6 = w4[6], q7 = w4[7];
    a0 = fma2(q4.x, e[8],  a0);
    a1 = fma2(q4.y, e[9],  a1);
    a2 = fma2(q5.x, e[10], a2);
    a3 = fma2(q5.y, e[11], a3);
    a0 = fma2(q6.x, e[12], a0);
    a1 = fma2(q6.y, e[13], a1);
    a2 = fma2(q7.x, e[14], a2);
    a3 = fma2(q7.y, e[15], a3);
    a0 = add2(a0, a1);
    a2 = add2(a2, a3);
    a0 = add2(a0, a2);
    float slo, shi;
    upk2(a0, slo, shi);
    return slo + shi;
}

// ---------------------------------------------------------------------------
// Fused kernel: 1 batch per 96-thread block.
//   warp 0: forward half-scan   (prob-space, renorm every 4 steps)
//   warp 1: backward half-scan
//   warp 2: gold-score gather   (latency-bound filler; writes g_gold)
// Meet: Z = sum_k (E^T alpha_511)_k gamma_512(k)
// ---------------------------------------------------------------------------
__global__ __launch_bounds__(96, 7)
void crf_fused_kernel(const float* __restrict__ logits,
                      const float* __restrict__ trans,
                      const int* __restrict__ tags,
                      const int* __restrict__ lengths) {
    const int w = threadIdx.x >> 5;     // 0 fwd, 1 bwd, 2 gold
    const int j = threadIdx.x & 31;     // lane = tag / seq-lane
    const int b = blockIdx.x;

    __shared__ __align__(16) float sbuf[2][2][32];  // [dir][parity][vec]
    __shared__ float xg[32];                        // gamma_512 exchange
    __shared__ float xacc;                          // bwd log-scale exchange

    const float* lg = logits + (size_t)b * (SEQ * TAGS);

    if (w == 2) {
        // ---- gold score: lanes stride over sequence positions ----
        const int* tg = tags + (size_t)b * SEQ;
        const int len = lengths[b];
        float acc = 0.0f;
        for (int s = j; s < len; s += 32) {
            int t1 = tg[s];
            acc += __ldg(&lg[s * TAGS + t1]);
            if (s > 0) {
                int t0 = tg[s - 1];
                acc += __ldg(&trans[t0 * TAGS + t1]);
            }
        }
#pragma unroll
        for (int k = 16; k; k >>= 1)
            acc += __shfl_xor_sync(0xffffffffu, acc, k);
        if (j == 0)
            g_gold[b] = acc;
        __syncthreads();        // match fb warps' single barrier
        return;
    }

    const int dir = w;          // 0 = fwd, 1 = bwd

    // E operand registers (pairs packed for fma2):
    //  fwd: e[k] = { E[2k][j],  E[2k+1][j] }   (pairs over i, column j)
    //  bwd: e[k] = { E[j][2k],  E[j][2k+1] }   (pairs over j', row i=lane)
    unsigned long long e[16];
    if (dir == 0) {
#pragma unroll
        for (int k = 0; k < 16; k++)
            e[k] = pk2(expf(trans[(2 * k)     * TAGS + j]),
                       expf(trans[(2 * k + 1) * TAGS + j]));
    } else {
#pragma unroll
        for (int k = 0; k < 16; k++)
            e[k] = pk2(expf(trans[j * TAGS + 2 * k]),
                       expf(trans[j * TAGS + 2 * k + 1]));
    }

    // init state (scaled by lane-0 emit)
    float e0 = (dir == 0) ? lg[j] : lg[(SEQ - 1) * TAGS + j];
    float m0 = __shfl_sync(0xffffffffu, e0, 0);
    float u      = ex2f((e0 - m0) * LOG2E);
    float logacc = m0;

    // emit stream: fwd rows 1,2,...,511   bwd rows 1022,1021,...,512
    const float* ep = (dir == 0) ? (lg + TAGS + j)
                                 : (lg + (SEQ - 2) * TAGS + j);
    const int estep = (dir == 0) ? TAGS : -TAGS;

    // prefetch ring depth 4 (all reads stay within this direction's half)
    float r0 = ep[0];
    float r1 = ep[estep];
    float r2 = ep[2 * estep];
    float r3 = ep[3 * estep];
    const float* pl = ep + 4 * estep;

    float* wb0 = &sbuf[dir][0][0];
    float* wb1 = &sbuf[dir][1][0];

#pragma unroll 4
    for (int it = 0; it < ITERS; ++it) {
        float emit = r0;
        r0 = r1; r1 = r2; r2 = r3;
        r3 = *pl; pl += estep;

        float p = ex2f(emit * LOG2E);       // off the carried chain

        float* wb = (it & 1) ? wb1 : wb0;
        wb[j] = u;
        __syncwarp(0xffffffffu);

        float w0;
        float s = matvec32(wb, e, w0);
        float un = s * p;

        if ((it & 3) == 0) {
            un *= rcpf(w0);                 // w0 comes from matvec's q0 reg
            logacc += lg2f(w0) * LN2;       // off-path bookkeeping
        }
        u = un;
    }

    // final renorm so the meeting dot-product can't overflow
    {
        float u0 = __shfl_sync(0xffffffffu, u, 0);
        u *= rcpf(u0);
        logacc += lg2f(u0) * LN2;
    }

    if (dir == 1) {
        xg[j] = u;                          // gamma_512 (scaled)
        if (j == 0) xacc = logacc;
    }
    __syncthreads();

    if (dir == 0) {
        // s = E^T alpha_511 (one more matvec, no emit). Parity-1 buffer:
        // its last reads (it=509) are sealed by syncwarp(it=510).
        wb1[j] = u;
        __syncwarp(0xffffffffu);
        float w0d;
        float s = matvec32(wb1, e, w0d);

        float prod = s * xg[j];
#pragma unroll
        for (int k = 16; k; k >>= 1)
            prod += __shfl_xor_sync(0xffffffffu, prod, k);

        if (j == 0)
            g_logz[b] = lg2f(prod) * LN2 + logacc + xacc;
    }
}

// ---------------------------------------------------------------------------
// Deterministic tree reduction -> mean(logz - gold)
// ---------------------------------------------------------------------------
__global__ void crf_reduce_kernel(float* __restrict__ out) {
    __shared__ float sm[256];
    int tid = threadIdx.x;
    float a = 0.0f;
#pragma unroll
    for (int o = 0; o < 4; o++) {
        int i = tid + o * 256;
        a += g_logz[i] - g_gold[i];
    }
    sm[tid] = a;
    __syncthreads();
#pragma unroll
    for (int k = 128; k; k >>= 1) {
        if (tid < k) sm[tid] += sm[tid + k];
        __syncthreads();
    }
    if (tid == 0) out[0] = sm[0] * (1.0f / 1024.0f);
}

extern "C" void kernel_launch(void* const* d_in, const int* in_sizes, int n_in,
                              void* d_out, int out_size) {
    const float* logits  = (const float*)d_in[0];
    const float* trans   = (const float*)d_in[1];
    const int*   tags    = (const int*)d_in[2];
    const int*   lengths = (const int*)d_in[3];
    float* out = (float*)d_out;

    crf_fused_kernel<<<BATCH, 96>>>(logits, trans, tags, lengths);
    crf_reduce_kernel<<<1, 256>>>(out);
}

// round 10
// speedup vs baseline: 1.1987x; 1.1987x over previous
#include <cuda_runtime.h>
#include <cuda_bf16.h>
#include <math.h>

#define BATCH 1024
#define SEQ   1024
#define TAGS  32
#define ITERS 511          // main-loop iterations per direction
#define NW    4            // warps per block in gold kernel

__device__ float g_logz[BATCH];
__device__ float g_gold[BATCH];

// ---------- packed f32x2 helpers (sm_103a FFMA2 path, PTX-only) ----------
__device__ __forceinline__ unsigned long long pk2(float x, float y) {
    unsigned long long r;
    asm("mov.b64 %0, {%1, %2};" : "=l"(r) : "f"(x), "f"(y));
    return r;
}
__device__ __forceinline__ void upk2(unsigned long long a, float& x, float& y) {
    asm("mov.b64 {%0, %1}, %2;" : "=f"(x), "=f"(y) : "l"(a));
}
__device__ __forceinline__ unsigned long long mul2(unsigned long long a, unsigned long long b) {
    unsigned long long d;
    asm("mul.rn.f32x2 %0, %1, %2;" : "=l"(d) : "l"(a), "l"(b));
    return d;
}
__device__ __forceinline__ unsigned long long fma2(unsigned long long a, unsigned long long b, unsigned long long c) {
    unsigned long long d;
    asm("fma.rn.f32x2 %0, %1, %2, %3;" : "=l"(d) : "l"(a), "l"(b), "l"(c));
    return d;
}
__device__ __forceinline__ unsigned long long add2(unsigned long long a, unsigned long long b) {
    unsigned long long d;
    asm("add.rn.f32x2 %0, %1, %2;" : "=l"(d) : "l"(a), "l"(b));
    return d;
}
__device__ __forceinline__ float ex2f(float x) {
    float y; asm("ex2.approx.f32 %0, %1;" : "=f"(y) : "f"(x)); return y;
}
__device__ __forceinline__ float lg2f(float x) {
    float y; asm("lg2.approx.f32 %0, %1;" : "=f"(y) : "f"(x)); return y;
}
__device__ __forceinline__ float rcpf(float x) {
    float y; asm("rcp.approx.f32 %0, %1;" : "=f"(y) : "f"(x)); return y;
}

#define LOG2E 1.4426950408889634f
#define LN2   0.6931471805599453f

// shared matvec: s_j = sum_i w_i * e-pairs. Returns w0 (= wb[0]) from the
// already-loaded q0 register so renorm never issues an extra on-chain LDS.
__device__ __forceinline__ float matvec32(const float* wb,
                                          const unsigned long long* e,
                                          float& w0_out) {
    const ulonglong2* w4 = (const ulonglong2*)wb;
    ulonglong2 q0 = w4[0], q1 = w4[1], q2 = w4[2], q3 = w4[3];
    {
        float a, bdum; upk2(q0.x, a, bdum); w0_out = a;
    }
    unsigned long long a0 = mul2(q0.x, e[0]);
    unsigned long long a1 = mul2(q0.y, e[1]);
    unsigned long long a2 = mul2(q1.x, e[2]);
    unsigned long long a3 = mul2(q1.y, e[3]);
    a0 = fma2(q2.x, e[4], a0);
    a1 = fma2(q2.y, e[5], a1);
    a2 = fma2(q3.x, e[6], a2);
    a3 = fma2(q3.y, e[7], a3);
    ulonglong2 q4 = w4[4], q5 = w4[5], q6 = w4[6], q7 = w4[7];
    a0 = fma2(q4.x, e[8],  a0);
    a1 = fma2(q4.y, e[9],  a1);
    a2 = fma2(q5.x, e[10], a2);
    a3 = fma2(q5.y, e[11], a3);
    a0 = fma2(q6.x, e[12], a0);
    a1 = fma2(q6.y, e[13], a1);
    a2 = fma2(q7.x, e[14], a2);
    a3 = fma2(q7.y, e[15], a3);
    a0 = add2(a0, a1);
    a2 = add2(a2, a3);
    a0 = add2(a0, a2);
    float slo, shi;
    upk2(a0, slo, shi);
    return slo + shi;
}

// ---------------------------------------------------------------------------
// Forward/backward kernel, 2 chains per warp for intra-warp ILP.
// Block = 64 threads, 2 batches (b0, b1):
//   warp 0: forward scans of b0 AND b1 (interleaved)
//   warp 1: backward scans of b0 AND b1
// Same direction per warp -> one shared e[16] register set, one __syncwarp
// covering both chains' STS per iteration.
// Prob-space recursion, renorm every 4 steps from the broadcast w[0].
// Meet: Z = sum_k (E^T alpha_511)_k gamma_512(k)
// ---------------------------------------------------------------------------
__global__ __launch_bounds__(64, 6)
void crf_fb_kernel(const float* __restrict__ logits,
                   const float* __restrict__ trans) {
    const int dir = threadIdx.x >> 5;   // 0 = fwd, 1 = bwd
    const int j   = threadIdx.x & 31;   // lane = tag
    const int b0  = blockIdx.x * 2;     // batches b0, b0+1

    __shared__ __align__(16) float sbuf[2][2][2][32]; // [dir][chain][parity][vec]
    __shared__ float xg[2][32];                       // gamma_512 exchange
    __shared__ float xacc[2];                         // bwd log-scale exchange

    // E operand registers (pairs packed for fma2):
    //  fwd: e[k] = { E[2k][j],  E[2k+1][j] }   (pairs over i, column j)
    //  bwd: e[k] = { E[j][2k],  E[j][2k+1] }   (pairs over j', row i=lane)
    unsigned long long e[16];
    if (dir == 0) {
#pragma unroll
        for (int k = 0; k < 16; k++)
            e[k] = pk2(expf(trans[(2 * k)     * TAGS + j]),
                       expf(trans[(2 * k + 1) * TAGS + j]));
    } else {
#pragma unroll
        for (int k = 0; k < 16; k++)
            e[k] = pk2(expf(trans[j * TAGS + 2 * k]),
                       expf(trans[j * TAGS + 2 * k + 1]));
    }

    const float* lgA = logits + (size_t)(b0)     * (SEQ * TAGS);
    const float* lgB = logits + (size_t)(b0 + 1) * (SEQ * TAGS);

    // init states (scaled by lane-0 emit)
    float eA = (dir == 0) ? lgA[j] : lgA[(SEQ - 1) * TAGS + j];
    float eB = (dir == 0) ? lgB[j] : lgB[(SEQ - 1) * TAGS + j];
    float mA = __shfl_sync(0xffffffffu, eA, 0);
    float mB = __shfl_sync(0xffffffffu, eB, 0);
    float uA = ex2f((eA - mA) * LOG2E);
    float uB = ex2f((eB - mB) * LOG2E);
    float accA = mA, accB = mB;

    // emit streams: fwd rows 1..511,  bwd rows 1022..512
    const int estep = (dir == 0) ? TAGS : -TAGS;
    const float* epA = (dir == 0) ? (lgA + TAGS + j) : (lgA + (SEQ - 2) * TAGS + j);
    const float* epB = (dir == 0) ? (lgB + TAGS + j) : (lgB + (SEQ - 2) * TAGS + j);

    // prefetch rings depth 4 (tail over-reads stay inside this half)
    float rA0 = epA[0], rA1 = epA[estep], rA2 = epA[2 * estep], rA3 = epA[3 * estep];
    float rB0 = epB[0], rB1 = epB[estep], rB2 = epB[2 * estep], rB3 = epB[3 * estep];
    const float* plA = epA + 4 * estep;
    const float* plB = epB + 4 * estep;

    float* wA0 = &sbuf[dir][0][0][0];
    float* wA1 = &sbuf[dir][0][1][0];
    float* wB0 = &sbuf[dir][1][0][0];
    float* wB1 = &sbuf[dir][1][1][0];

#pragma unroll 4
    for (int it = 0; it < ITERS; ++it) {
        float emA = rA0, emB = rB0;
        rA0 = rA1; rA1 = rA2; rA2 = rA3;
        rB0 = rB1; rB1 = rB2; rB2 = rB3;
        rA3 = *plA; plA += estep;
        rB3 = *plB; plB += estep;

        float pA = ex2f(emA * LOG2E);       // off the carried chains
        float pB = ex2f(emB * LOG2E);

        float* wbA = (it & 1) ? wA1 : wA0;
        float* wbB = (it & 1) ? wB1 : wB0;
        wbA[j] = uA;
        wbB[j] = uB;
        __syncwarp(0xffffffffu);            // one sync covers both chains

        float w0A, w0B;
        float sA = matvec32(wbA, e, w0A);   // two independent trees interleave
        float sB = matvec32(wbB, e, w0B);
        float unA = sA * pA;
        float unB = sB * pB;

        if ((it & 3) == 0) {
            unA *= rcpf(w0A);
            unB *= rcpf(w0B);
            accA += lg2f(w0A) * LN2;        // off-path bookkeeping
            accB += lg2f(w0B) * LN2;
        }
        uA = unA;
        uB = unB;
    }

    // final renorm so the meeting dot-products can't overflow
    {
        float u0A = __shfl_sync(0xffffffffu, uA, 0);
        float u0B = __shfl_sync(0xffffffffu, uB, 0);
        uA *= rcpf(u0A);
        uB *= rcpf(u0B);
        accA += lg2f(u0A) * LN2;
        accB += lg2f(u0B) * LN2;
    }

    if (dir == 1) {
        xg[0][j] = uA;                      // gamma_512 (scaled)
        xg[1][j] = uB;
        if (j == 0) { xacc[0] = accA; xacc[1] = accB; }
    }
    __syncthreads();

    if (dir == 0) {
        // s = E^T alpha_511 (one more matvec each, no emit). Parity-1 buffers:
        // their last reads (it=509) are sealed by syncwarp(it=510).
        wA1[j] = uA;
        wB1[j] = uB;
        __syncwarp(0xffffffffu);
        float d0, d1;
        float sA = matvec32(wA1, e, d0);
        float sB = matvec32(wB1, e, d1);

        float prA = sA * xg[0][j];
        float prB = sB * xg[1][j];
#pragma unroll
        for (int k = 16; k; k >>= 1) {
            prA += __shfl_xor_sync(0xffffffffu, prA, k);
            prB += __shfl_xor_sync(0xffffffffu, prB, k);
        }

        if (j == 0) {
            g_logz[b0]     = lg2f(prA) * LN2 + accA + xacc[0];
            g_logz[b0 + 1] = lg2f(prB) * LN2 + accB + xacc[1];
        }
    }
}

// ---------------------------------------------------------------------------
// Gold score per batch (separate kernel — fusing it into fb blocks floods the
// per-SM L1tex wavefront queue with 32-line gathers; measured +39us in R9).
// ---------------------------------------------------------------------------
__global__ __launch_bounds__(NW * 32, 1)
void crf_gold_kernel(const float* __restrict__ logits,
                     const float* __restrict__ trans,
                     const int* __restrict__ tags,
                     const int* __restrict__ lengths) {
    __shared__ float tr[TAGS * TAGS];
    for (int i = threadIdx.x; i < TAGS * TAGS; i += blockDim.x)
        tr[i] = trans[i];
    __syncthreads();

    const int warp = threadIdx.x >> 5;
    const int l    = threadIdx.x & 31;
    const int b    = blockIdx.x * NW + warp;

    const int*   tg = tags + (size_t)b * SEQ;
    const float* lg = logits + (size_t)b * (SEQ * TAGS);
    const int len = lengths[b];

    float acc = 0.0f;
    for (int s = l; s < len; s += 32) {
        int t1 = tg[s];
        acc += lg[s * TAGS + t1];
        if (s > 0) {
            int t0 = tg[s - 1];
            acc += tr[t0 * TAGS + t1];
        }
    }
#pragma unroll
    for (int k = 16; k; k >>= 1)
        acc += __shfl_xor_sync(0xffffffffu, acc, k);
    if (l == 0)
        g_gold[b] = acc;
}

// ---------------------------------------------------------------------------
// Deterministic tree reduction -> mean(logz - gold)
// ---------------------------------------------------------------------------
__global__ void crf_reduce_kernel(float* __restrict__ out) {
    __shared__ float sm[256];
    int tid = threadIdx.x;
    float a = 0.0f;
#pragma unroll
    for (int o = 0; o < 4; o++) {
        int i = tid + o * 256;
        a += g_logz[i] - g_gold[i];
    }
    sm[tid] = a;
    __syncthreads();
#pragma unroll
    for (int k = 128; k; k >>= 1) {
        if (tid < k) sm[tid] += sm[tid + k];
        __syncthreads();
    }
    if (tid == 0) out[0] = sm[0] * (1.0f / 1024.0f);
}

extern "C" void kernel_launch(void* const* d_in, const int* in_sizes, int n_in,
                              void* d_out, int out_size) {
    const float* logits  = (const float*)d_in[0];
    const float* trans   = (const float*)d_in[1];
    const int*   tags    = (const int*)d_in[2];
    const int*   lengths = (const int*)d_in[3];
    float* out = (float*)d_out;

    crf_fb_kernel<<<BATCH / 2, 64>>>(logits, trans);
    crf_gold_kernel<<<BATCH / NW, NW * 32>>>(logits, trans, tags, lengths);
    crf_reduce_kernel<<<1, 256>>>(out);
}

// round 11
// speedup vs baseline: 1.4421x; 1.2031x over previous
#include <cuda_runtime.h>
#include <cuda_bf16.h>
#include <math.h>

#define BATCH 1024
#define SEQ   1024
#define TAGS  32
#define ITERS 511          // main-loop iterations per direction
#define PF    8            // emit prefetch ring depth

__device__ float g_logz[BATCH];
__device__ float g_partial[BATCH];
__device__ unsigned int g_ticket;

// ---------- packed f32x2 helpers (sm_103a FFMA2 path, PTX-only) ----------
__device__ __forceinline__ unsigned long long pk2(float x, float y) {
    unsigned long long r;
    asm("mov.b64 %0, {%1, %2};" : "=l"(r) : "f"(x), "f"(y));
    return r;
}
__device__ __forceinline__ void upk2(unsigned long long a, float& x, float& y) {
    asm("mov.b64 {%0, %1}, %2;" : "=f"(x), "=f"(y) : "l"(a));
}
__device__ __forceinline__ unsigned long long mul2(unsigned long long a, unsigned long long b) {
    unsigned long long d;
    asm("mul.rn.f32x2 %0, %1, %2;" : "=l"(d) : "l"(a), "l"(b));
    return d;
}
__device__ __forceinline__ unsigned long long fma2(unsigned long long a, unsigned long long b, unsigned long long c) {
    unsigned long long d;
    asm("fma.rn.f32x2 %0, %1, %2, %3;" : "=l"(d) : "l"(a), "l"(b), "l"(c));
    return d;
}
__device__ __forceinline__ unsigned long long add2(unsigned long long a, unsigned long long b) {
    unsigned long long d;
    asm("add.rn.f32x2 %0, %1, %2;" : "=l"(d) : "l"(a), "l"(b));
    return d;
}
__device__ __forceinline__ float ex2f(float x) {
    float y; asm("ex2.approx.f32 %0, %1;" : "=f"(y) : "f"(x)); return y;
}
__device__ __forceinline__ float lg2f(float x) {
    float y; asm("lg2.approx.f32 %0, %1;" : "=f"(y) : "f"(x)); return y;
}
__device__ __forceinline__ float rcpf(float x) {
    float y; asm("rcp.approx.f32 %0, %1;" : "=f"(y) : "f"(x)); return y;
}

#define LOG2E 1.4426950408889634f
#define LN2   0.6931471805599453f

// shared matvec: s_j = sum_i w_i * e-pairs. Returns w0 (= wb[0]) from the
// already-loaded q0 register so renorm never issues an extra on-chain LDS.
__device__ __forceinline__ float matvec32(const float* wb,
                                          const unsigned long long* e,
                                          float& w0_out) {
    const ulonglong2* w4 = (const ulonglong2*)wb;
    ulonglong2 q0 = w4[0], q1 = w4[1], q2 = w4[2], q3 = w4[3];
    {
        float a, bdum; upk2(q0.x, a, bdum); w0_out = a;
    }
    unsigned long long a0 = mul2(q0.x, e[0]);
    unsigned long long a1 = mul2(q0.y, e[1]);
    unsigned long long a2 = mul2(q1.x, e[2]);
    unsigned long long a3 = mul2(q1.y, e[3]);
    a0 = fma2(q2.x, e[4], a0);
    a1 = fma2(q2.y, e[5], a1);
    a2 = fma2(q3.x, e[6], a2);
    a3 = fma2(q3.y, e[7], a3);
    ulonglong2 q4 = w4[4], q5 = w4[5], q6 = w4[6], q7 = w4[7];
    a0 = fma2(q4.x, e[8],  a0);
    a1 = fma2(q4.y, e[9],  a1);
    a2 = fma2(q5.x, e[10], a2);
    a3 = fma2(q5.y, e[11], a3);
    a0 = fma2(q6.x, e[12], a0);
    a1 = fma2(q6.y, e[13], a1);
    a2 = fma2(q7.x, e[14], a2);
    a3 = fma2(q7.y, e[15], a3);
    a0 = add2(a0, a1);
    a2 = add2(a2, a3);
    a0 = add2(a0, a2);
    float slo, shi;
    upk2(a0, slo, shi);
    return slo + shi;
}

// ---------------------------------------------------------------------------
// Forward+backward kernel (R8 structure: 1 chain per warp, 2048 warps).
// 2 batches per block (128 threads):
//   warp 0: fwd b0   warp 1: bwd b0   warp 2: fwd b1   warp 3: bwd b1
// Probability-space recursion, renorm every 4 steps from the broadcast w[0].
// Emit stream prefetched PF=8 deep (MLP=8 vs 4: halves exposed DRAM latency,
// which R10 analysis identified as the 350cyc/iter binder).
// Meet: Z = sum_k (E^T alpha_511)_k gamma_512(k)
// ---------------------------------------------------------------------------
__global__ __launch_bounds__(128, 4)
void crf_fb_kernel(const float* __restrict__ logits,
                   const float* __restrict__ trans) {
    const int w   = threadIdx.x >> 5;     // warp in block (0..3)
    const int j   = threadIdx.x & 31;     // lane = tag
    const int bi  = w >> 1;               // batch within block (0/1)
    const int dir = w & 1;                // 0 = fwd, 1 = bwd
    const int b   = blockIdx.x * 2 + bi;

    __shared__ __align__(16) float sbuf[4][2][32];  // [warp][parity][vec]
    __shared__ float xg[2][32];                     // gamma_512 exchange
    __shared__ float xacc[2];                       // bwd log-scale exchange

    // E operand registers (pairs packed for fma2):
    //  fwd: e[k] = { E[2k][j],  E[2k+1][j] }   (pairs over i, column j)
    //  bwd: e[k] = { E[j][2k],  E[j][2k+1] }   (pairs over j', row i=lane)
    unsigned long long e[16];
    if (dir == 0) {
#pragma unroll
        for (int k = 0; k < 16; k++)
            e[k] = pk2(expf(trans[(2 * k)     * TAGS + j]),
                       expf(trans[(2 * k + 1) * TAGS + j]));
    } else {
#pragma unroll
        for (int k = 0; k < 16; k++)
            e[k] = pk2(expf(trans[j * TAGS + 2 * k]),
                       expf(trans[j * TAGS + 2 * k + 1]));
    }

    const float* lg = logits + (size_t)b * (SEQ * TAGS);

    // init state (scaled by lane-0 emit)
    float e0 = (dir == 0) ? lg[j] : lg[(SEQ - 1) * TAGS + j];
    float m0 = __shfl_sync(0xffffffffu, e0, 0);
    float u      = ex2f((e0 - m0) * LOG2E);
    float logacc = m0;

    // emit stream: fwd rows 1..511, bwd rows 1022..512.
    // Ring depth PF=8; tail over-reads stay in-bounds (fwd<=519, bwd>=504).
    const int estep = (dir == 0) ? TAGS : -TAGS;
    const float* ep = (dir == 0) ? (lg + TAGS + j)
                                 : (lg + (SEQ - 2) * TAGS + j);
    float r[PF];
#pragma unroll
    for (int k = 0; k < PF; k++)
        r[k] = ep[k * estep];
    const float* pl = ep + PF * estep;

    float* wb0 = &sbuf[w][0][0];
    float* wb1 = &sbuf[w][1][0];

#pragma unroll 8
    for (int it = 0; it < ITERS; ++it) {
        float emit = r[it & (PF - 1)];
        r[it & (PF - 1)] = *pl;             // refill same slot (needed it+8)
        pl += estep;

        float p = ex2f(emit * LOG2E);       // off the carried chain

        float* wb = (it & 1) ? wb1 : wb0;
        wb[j] = u;
        __syncwarp(0xffffffffu);

        float w0;
        float s = matvec32(wb, e, w0);
        float un = s * p;

        if ((it & 3) == 0) {
            un *= rcpf(w0);                 // w0 from matvec's q0 register
            logacc += lg2f(w0) * LN2;       // off-path bookkeeping
        }
        u = un;
    }

    // final renorm so the meeting dot-product can't overflow
    {
        float u0 = __shfl_sync(0xffffffffu, u, 0);
        u *= rcpf(u0);
        logacc += lg2f(u0) * LN2;
    }

    if (dir == 1) {
        xg[bi][j] = u;                      // gamma_512 (scaled)
        if (j == 0) xacc[bi] = logacc;
    }
    __syncthreads();

    if (dir == 0) {
        // s = E^T alpha_511 (one more matvec, no emit). Parity-1 buffer:
        // its last reads (it=509) are sealed by syncwarp(it=510).
        wb1[j] = u;
        __syncwarp(0xffffffffu);
        float w0d;
        float s = matvec32(wb1, e, w0d);

        float prod = s * xg[bi][j];
#pragma unroll
        for (int k = 16; k; k >>= 1)
            prod += __shfl_xor_sync(0xffffffffu, prod, k);

        if (j == 0)
            g_logz[b] = lg2f(prod) * LN2 + logacc + xacc[bi];
    }
}

// ---------------------------------------------------------------------------
// Gold score: one 128-thread block per batch (4x the gather-latency hiding of
// the old 1-warp-per-batch layout). The LAST block to finish also performs the
// final deterministic reduction (threadfence-ticket pattern), eliminating the
// separate reduce kernel launch. Ticket is reset for graph-replay determinism.
// ---------------------------------------------------------------------------
__global__ __launch_bounds__(128, 8)
void crf_gold_reduce_kernel(const float* __restrict__ logits,
                            const float* __restrict__ trans,
                            const int* __restrict__ tags,
                            const int* __restrict__ lengths,
                            float* __restrict__ out) {
    __shared__ float tr[TAGS * TAGS];
    __shared__ float sm[4];
    __shared__ bool  amLast;

    for (int i = threadIdx.x; i < TAGS * TAGS; i += blockDim.x)
        tr[i] = trans[i];
    __syncthreads();

    const int b    = blockIdx.x;
    const int tid  = threadIdx.x;
    const int warp = tid >> 5;
    const int l    = tid & 31;

    const int*   tg = tags + (size_t)b * SEQ;
    const float* lg = logits + (size_t)b * (SEQ * TAGS);
    const int len = lengths[b];

    float acc = 0.0f;
    for (int s = tid; s < len; s += 128) {
        int t1 = __ldg(&tg[s]);
        acc += __ldg(&lg[s * TAGS + t1]);
        if (s > 0) {
            int t0 = __ldg(&tg[s - 1]);
            acc += tr[t0 * TAGS + t1];
        }
    }
#pragma unroll
    for (int k = 16; k; k >>= 1)
        acc += __shfl_xor_sync(0xffffffffu, acc, k);
    if (l == 0) sm[warp] = acc;
    __syncthreads();

    if (tid == 0) {
        float gold = sm[0] + sm[1] + sm[2] + sm[3];
        g_partial[b] = g_logz[b] - gold;
        __threadfence();
        unsigned int t = atomicAdd(&g_ticket, 1u);
        amLast = (t == (unsigned)(BATCH - 1));
    }
    __syncthreads();

    if (amLast) {
        // deterministic tree reduction over the 1024 partials
        __shared__ float red[128];
        float a = 0.0f;
#pragma unroll
        for (int o = 0; o < 8; o++)
            a += __ldcg(&g_partial[tid + o * 128]);
        red[tid] = a;
        __syncthreads();
#pragma unroll
        for (int k = 64; k; k >>= 1) {
            if (tid < k) red[tid] += red[tid + k];
            __syncthreads();
        }
        if (tid == 0) {
            out[0] = red[0] * (1.0f / 1024.0f);
            g_ticket = 0;                  // reset for next graph replay
        }
    }
}

extern "C" void kernel_launch(void* const* d_in, const int* in_sizes, int n_in,
                              void* d_out, int out_size) {
    const float* logits  = (const float*)d_in[0];
    const float* trans   = (const float*)d_in[1];
    const int*   tags    = (const int*)d_in[2];
    const int*   lengths = (const int*)d_in[3];
    float* out = (float*)d_out;

    crf_fb_kernel<<<BATCH / 2, 128>>>(logits, trans);
    crf_gold_reduce_kernel<<<BATCH, 128>>>(logits, trans, tags, lengths, out);
}